// round 1
// baseline (speedup 1.0000x reference)
#include <cuda_runtime.h>

#define Bsz  8
#define Cdim 256
#define Ntok 4096

// Scratch (allocation-free rule: __device__ globals). Token-major [B][N][C].
__device__ float g_q[Bsz * Ntok * Cdim];
__device__ float g_k[Bsz * Ntok * Cdim];
__device__ float g_v[Bsz * Ntok * Cdim];

// ---------------------------------------------------------------------------
// Projection: out[b,n,o] = sum_c W[o,c] * x[b,c,n] + bias[o]
// One SGEMM per (proj, batch). Block tile 64n x 64o, 256 threads, 4x4 micro.
// ---------------------------------------------------------------------------
__global__ __launch_bounds__(256) void proj_kernel(
    const float* __restrict__ x,
    const float* __restrict__ wq, const float* __restrict__ bq,
    const float* __restrict__ wk, const float* __restrict__ bk,
    const float* __restrict__ wv, const float* __restrict__ bv)
{
    int z    = blockIdx.z;      // 0..23
    int proj = z >> 3;          // 0=q 1=k 2=v
    int b    = z & 7;

    const float* W; const float* bias; float* out;
    if (proj == 0)      { W = wq; bias = bq; out = g_q; }
    else if (proj == 1) { W = wk; bias = bk; out = g_k; }
    else                { W = wv; bias = bv; out = g_v; }

    int n0 = blockIdx.x * 64;
    int o0 = blockIdx.y * 64;

    __shared__ float Xs[16][64];
    __shared__ float Ws[16][65];

    int tid = threadIdx.x;
    int ty = tid >> 4, tx = tid & 15;

    float acc[4][4];
    #pragma unroll
    for (int i = 0; i < 4; i++)
        #pragma unroll
        for (int j = 0; j < 4; j++) acc[i][j] = 0.f;

    const float* xb = x + (size_t)b * Cdim * Ntok;

    for (int c0 = 0; c0 < Cdim; c0 += 16) {
        #pragma unroll
        for (int r = 0; r < 4; r++) {
            int idx = tid + 256 * r;
            int cc = idx >> 6, nn = idx & 63;
            Xs[cc][nn] = xb[(size_t)(c0 + cc) * Ntok + n0 + nn];
        }
        #pragma unroll
        for (int r = 0; r < 4; r++) {
            int idx = tid + 256 * r;
            int oo = idx >> 4, cc = idx & 15;
            Ws[cc][oo] = W[(size_t)(o0 + oo) * Cdim + c0 + cc];
        }
        __syncthreads();
        #pragma unroll
        for (int cc = 0; cc < 16; cc++) {
            float a[4], w4[4];
            #pragma unroll
            for (int i = 0; i < 4; i++) a[i] = Xs[cc][ty * 4 + i];
            #pragma unroll
            for (int j = 0; j < 4; j++) w4[j] = Ws[cc][tx * 4 + j];
            #pragma unroll
            for (int i = 0; i < 4; i++)
                #pragma unroll
                for (int j = 0; j < 4; j++)
                    acc[i][j] += a[i] * w4[j];
        }
        __syncthreads();
    }

    float* ob = out + (size_t)b * Ntok * Cdim;
    #pragma unroll
    for (int i = 0; i < 4; i++) {
        int n = n0 + ty * 4 + i;
        #pragma unroll
        for (int j = 0; j < 4; j++) {
            int o = o0 + tx * 4 + j;
            ob[(size_t)n * Cdim + o] = acc[i][j] + bias[o];
        }
    }
}

// ---------------------------------------------------------------------------
// Flash attention, fp32. Block = (b, 64-query tile), 256 threads.
// Warp w owns queries w*8..w*8+7; lane owns channels {lane, lane+32, ...}.
// S-phase: each lane computes 8q x 2m dot products from SMEM (Q transposed,
// K natural with padded stride). Online softmax stats replicated per-lane.
// ---------------------------------------------------------------------------
#define QT_STRIDE 68
#define KS_STRIDE 257
#define PS_STRIDE 65
#define SMEM_FLOATS (256 * QT_STRIDE + 64 * KS_STRIDE + 64 * 256 + 64 * PS_STRIDE)
#define SMEM_BYTES  (SMEM_FLOATS * 4)

__global__ __launch_bounds__(256, 1) void attn_kernel(
    const float* __restrict__ x,
    const float* __restrict__ gamma_p,
    float* __restrict__ out)
{
    extern __shared__ float sm[];
    float* QT = sm;                         // [256][QT_STRIDE]  Q transposed [c][q]
    float* KS = QT + 256 * QT_STRIDE;       // [64][KS_STRIDE]   K natural   [m][c]
    float* VS = KS + 64 * KS_STRIDE;        // [64][256]         V natural   [m][c]
    float* PS = VS + 64 * 256;              // [64][PS_STRIDE]   P           [q][m]

    int b  = blockIdx.y;
    int q0 = blockIdx.x * 64;
    int tid  = threadIdx.x;
    int warp = tid >> 5;
    int lane = tid & 31;

    const float* Qg = g_q + ((size_t)b * Ntok + q0) * Cdim;
    const float* Kg = g_k + (size_t)b * Ntok * Cdim;
    const float* Vg = g_v + (size_t)b * Ntok * Cdim;

    // Stage Q tile transposed (once per block; store conflicts amortized).
    for (int idx = tid; idx < 64 * 64; idx += 256) {
        int m = idx >> 6, c4 = idx & 63;
        float4 v4 = *(const float4*)(Qg + (size_t)m * Cdim + c4 * 4);
        QT[(c4 * 4 + 0) * QT_STRIDE + m] = v4.x;
        QT[(c4 * 4 + 1) * QT_STRIDE + m] = v4.y;
        QT[(c4 * 4 + 2) * QT_STRIDE + m] = v4.z;
        QT[(c4 * 4 + 3) * QT_STRIDE + m] = v4.w;
    }

    float acc[8][8];
    #pragma unroll
    for (int i = 0; i < 8; i++)
        #pragma unroll
        for (int j = 0; j < 8; j++) acc[i][j] = 0.f;
    float mrun[8], lrun[8];
    #pragma unroll
    for (int i = 0; i < 8; i++) { mrun[i] = -1e30f; lrun[i] = 0.f; }

    for (int kt = 0; kt < 64; kt++) {
        int m0 = kt * 64;
        __syncthreads();  // protect previous iteration's KS/VS/PS reads (and QT stage)

        for (int idx = tid; idx < 64 * 64; idx += 256) {
            int m = idx >> 6, c4 = idx & 63;
            float4 k4 = *(const float4*)(Kg + (size_t)(m0 + m) * Cdim + c4 * 4);
            KS[m * KS_STRIDE + c4 * 4 + 0] = k4.x;
            KS[m * KS_STRIDE + c4 * 4 + 1] = k4.y;
            KS[m * KS_STRIDE + c4 * 4 + 2] = k4.z;
            KS[m * KS_STRIDE + c4 * 4 + 3] = k4.w;
            float4 v4 = *(const float4*)(Vg + (size_t)(m0 + m) * Cdim + c4 * 4);
            *(float4*)(VS + m * 256 + c4 * 4) = v4;
        }
        __syncthreads();

        // ---- S = Q . K^T for 8 queries x 2 keys per lane ----
        float s[8][2];
        #pragma unroll
        for (int i = 0; i < 8; i++) { s[i][0] = 0.f; s[i][1] = 0.f; }

        const float* ksp0 = KS + (lane * 2 + 0) * KS_STRIDE;
        const float* ksp1 = KS + (lane * 2 + 1) * KS_STRIDE;
        #pragma unroll 4
        for (int cc = 0; cc < 256; cc++) {
            float4 qa = *(const float4*)(QT + cc * QT_STRIDE + warp * 8);
            float4 qb = *(const float4*)(QT + cc * QT_STRIDE + warp * 8 + 4);
            float k0 = ksp0[cc];
            float k1 = ksp1[cc];
            float qv[8] = {qa.x, qa.y, qa.z, qa.w, qb.x, qb.y, qb.z, qb.w};
            #pragma unroll
            for (int i = 0; i < 8; i++) {
                s[i][0] += qv[i] * k0;
                s[i][1] += qv[i] * k1;
            }
        }

        // ---- online softmax update (stats replicated across lanes) ----
        float al[8];
        #pragma unroll
        for (int i = 0; i < 8; i++) {
            float tm = fmaxf(s[i][0], s[i][1]);
            #pragma unroll
            for (int off = 16; off >= 1; off >>= 1)
                tm = fmaxf(tm, __shfl_xor_sync(0xffffffffu, tm, off));
            float mnew = fmaxf(mrun[i], tm);
            float a  = __expf(mrun[i] - mnew);
            float p0 = __expf(s[i][0] - mnew);
            float p1 = __expf(s[i][1] - mnew);
            float rs = p0 + p1;
            #pragma unroll
            for (int off = 16; off >= 1; off >>= 1)
                rs += __shfl_xor_sync(0xffffffffu, rs, off);
            lrun[i] = lrun[i] * a + rs;
            mrun[i] = mnew;
            al[i]   = a;
            PS[(warp * 8 + i) * PS_STRIDE + lane * 2 + 0] = p0;
            PS[(warp * 8 + i) * PS_STRIDE + lane * 2 + 1] = p1;
        }
        __syncthreads();

        // ---- acc = acc*alpha + P @ V ----
        #pragma unroll
        for (int i = 0; i < 8; i++)
            #pragma unroll
            for (int j = 0; j < 8; j++) acc[i][j] *= al[i];

        #pragma unroll 2
        for (int m = 0; m < 64; m++) {
            float vv[8];
            #pragma unroll
            for (int j = 0; j < 8; j++) vv[j] = VS[m * 256 + lane + 32 * j];
            #pragma unroll
            for (int i = 0; i < 8; i++) {
                float p = PS[(warp * 8 + i) * PS_STRIDE + m];
                #pragma unroll
                for (int j = 0; j < 8; j++) acc[i][j] += p * vv[j];
            }
        }
    }

    // ---- epilogue: out[b,c,n] = gamma * attn/l + x[b,c,n] ----
    float g = gamma_p[0];
    const float* xb = x   + (size_t)b * Cdim * Ntok;
    float*       ob = out + (size_t)b * Cdim * Ntok;
    #pragma unroll
    for (int i = 0; i < 8; i++) {
        int n = q0 + warp * 8 + i;
        float inv = 1.f / lrun[i];
        #pragma unroll
        for (int j = 0; j < 8; j++) {
            int c = lane + 32 * j;
            ob[(size_t)c * Ntok + n] = g * acc[i][j] * inv + xb[(size_t)c * Ntok + n];
        }
    }
}

// ---------------------------------------------------------------------------
extern "C" void kernel_launch(void* const* d_in, const int* in_sizes, int n_in,
                              void* d_out, int out_size)
{
    const float* x     = (const float*)d_in[0];
    const float* wq    = (const float*)d_in[1];
    const float* bq    = (const float*)d_in[2];
    const float* wk    = (const float*)d_in[3];
    const float* bk    = (const float*)d_in[4];
    const float* wv    = (const float*)d_in[5];
    const float* bv    = (const float*)d_in[6];
    const float* gamma = (const float*)d_in[7];

    dim3 pgrid(Ntok / 64, Cdim / 64, 3 * Bsz);
    proj_kernel<<<pgrid, 256>>>(x, wq, bq, wk, bk, wv, bv);

    cudaFuncSetAttribute(attn_kernel,
                         cudaFuncAttributeMaxDynamicSharedMemorySize, SMEM_BYTES);
    dim3 agrid(Ntok / 64, Bsz);
    attn_kernel<<<agrid, 256, SMEM_BYTES>>>(x, gamma, (float*)d_out);
}

// round 6
// speedup vs baseline: 2.8635x; 2.8635x over previous
#include <cuda_runtime.h>
#include <cstdint>

#define Bsz  8
#define Cdim 256
#define Ntok 4096

// Scratch (allocation-free rule): token-major [B][N][C]
__device__ float g_q[Bsz * Ntok * Cdim];
__device__ float g_k[Bsz * Ntok * Cdim];
__device__ float g_v[Bsz * Ntok * Cdim];

// ---------------------------------------------------------------------------
// m16n8k8 tf32 mma: A row-major (16x8), B col-major (8x8), fp32 accum.
// ---------------------------------------------------------------------------
__device__ __forceinline__ void mma_tf32(float* c,
    uint32_t a0, uint32_t a1, uint32_t a2, uint32_t a3,
    uint32_t b0, uint32_t b1)
{
    asm volatile(
        "mma.sync.aligned.m16n8k8.row.col.f32.tf32.tf32.f32 "
        "{%0,%1,%2,%3}, {%4,%5,%6,%7}, {%8,%9}, {%0,%1,%2,%3};\n"
        : "+f"(c[0]), "+f"(c[1]), "+f"(c[2]), "+f"(c[3])
        : "r"(a0), "r"(a1), "r"(a2), "r"(a3), "r"(b0), "r"(b1));
}

// ---------------------------------------------------------------------------
// Projection via tf32 mma: out[b,n,o] = sum_c W[o,c] x[b,c,n] + bias[o]
// Block: 64n x 64o tile, 256 threads (8 warps: 4 row strips x 2 col halves).
// ---------------------------------------------------------------------------
#define PX_S 72
#define PW_S 260
#define PROJ_SMEM ((256 * PX_S + 64 * PW_S) * 4)

__global__ __launch_bounds__(256, 1) void proj_mma_kernel(
    const float* __restrict__ x,
    const float* __restrict__ wq, const float* __restrict__ bq,
    const float* __restrict__ wk, const float* __restrict__ bk,
    const float* __restrict__ wv, const float* __restrict__ bv)
{
    int z    = blockIdx.z;
    int proj = z >> 3;
    int b    = z & 7;

    const float* W; const float* bias; float* out;
    if (proj == 0)      { W = wq; bias = bq; out = g_q; }
    else if (proj == 1) { W = wk; bias = bk; out = g_k; }
    else                { W = wv; bias = bv; out = g_v; }

    int n0 = blockIdx.x * 64;
    int o0 = blockIdx.y * 64;

    extern __shared__ float sm[];
    float* Xs = sm;                 // [256 c][PX_S]  x[c][n]
    float* Ws = sm + 256 * PX_S;    // [64 o][PW_S]   W[o][c]

    int tid  = threadIdx.x;
    int warp = tid >> 5, lane = tid & 31;
    int strip = warp & 3, half = warp >> 2;
    int g = lane >> 2, tig = lane & 3;

    const float* xb = x + (size_t)b * Cdim * Ntok;
    for (int i = tid; i < 4096; i += 256) {
        int cc = i >> 4, n4 = i & 15;
        float4 v = *(const float4*)(xb + (size_t)cc * Ntok + n0 + n4 * 4);
        *(float4*)(Xs + cc * PX_S + n4 * 4) = v;
    }
    for (int i = tid; i < 4096; i += 256) {
        int oo = i >> 6, c4 = i & 63;
        float4 v = *(const float4*)(W + (size_t)(o0 + oo) * Cdim + c4 * 4);
        *(float4*)(Ws + oo * PW_S + c4 * 4) = v;
    }
    __syncthreads();

    float acc[4][4];
    #pragma unroll
    for (int i = 0; i < 4; i++)
        #pragma unroll
        for (int j = 0; j < 4; j++) acc[i][j] = 0.f;

    for (int k0 = 0; k0 < 256; k0 += 8) {
        // A[n][c] = x[c][n]: a0 row=strip16+g col=k0+tig
        const float* ap = Xs + (k0 + tig) * PX_S + strip * 16 + g;
        uint32_t a0 = __float_as_uint(ap[0]);
        uint32_t a1 = __float_as_uint(ap[8]);
        uint32_t a2 = __float_as_uint(ap[4 * PX_S]);
        uint32_t a3 = __float_as_uint(ap[4 * PX_S + 8]);
        #pragma unroll
        for (int nt = 0; nt < 4; nt++) {
            int o = half * 32 + nt * 8 + g;
            const float* bp = Ws + o * PW_S + k0 + tig;
            mma_tf32(acc[nt], a0, a1, a2, a3,
                     __float_as_uint(bp[0]), __float_as_uint(bp[4]));
        }
    }

    float* ob = out + ((size_t)b * Ntok + n0) * Cdim;
    int n1 = strip * 16 + g;
    #pragma unroll
    for (int nt = 0; nt < 4; nt++) {
        int o = o0 + half * 32 + nt * 8 + tig * 2;
        float b0v = bias[o], b1v = bias[o + 1];
        *(float2*)(ob + (size_t)n1 * Cdim + o) =
            make_float2(acc[nt][0] + b0v, acc[nt][1] + b1v);
        *(float2*)(ob + (size_t)(n1 + 8) * Cdim + o) =
            make_float2(acc[nt][2] + b0v, acc[nt][3] + b1v);
    }
}

// ---------------------------------------------------------------------------
// Flash attention with tf32 mma. Block = 64 queries, 256 threads (8 warps).
// S phase: warp(strip,half) computes S[16 rows][32 keys]. Online softmax with
// cross-half exchange through SMEM. PV: warp computes O[16 rows][128 chans].
// ---------------------------------------------------------------------------
#define QS_S 260
#define KS_S 260
#define VS_S 264
#define PS_S 68
#define ATTN_SMEM_FLOATS (64*QS_S + 64*KS_S + 64*VS_S + 64*PS_S + 256)
#define ATTN_SMEM (ATTN_SMEM_FLOATS * 4)

__global__ __launch_bounds__(256, 1) void attn_mma_kernel(
    const float* __restrict__ x,
    const float* __restrict__ gamma_p,
    float* __restrict__ out)
{
    extern __shared__ float sm[];
    float* QS   = sm;                  // [64 q][QS_S]  Q[q][c]
    float* KS   = QS + 64 * QS_S;      // [64 m][KS_S]  K[m][c]
    float* VS   = KS + 64 * KS_S;      // [64 m][VS_S]  V[m][c]
    float* PS   = VS + 64 * VS_S;      // [64 q][PS_S]  P[q][m]
    float* RMAX = PS + 64 * PS_S;      // [2][64]
    float* RSUM = RMAX + 128;          // [2][64]

    int b  = blockIdx.y;
    int q0 = blockIdx.x * 64;
    int tid  = threadIdx.x;
    int warp = tid >> 5, lane = tid & 31;
    int strip = warp & 3, half = warp >> 2;
    int g = lane >> 2, tig = lane & 3;
    int r1 = strip * 16 + g;           // frag rows r1, r1+8 (0..63)

    const float* Qg = g_q + ((size_t)b * Ntok + q0) * Cdim;
    const float* Kg = g_k + (size_t)b * Ntok * Cdim;
    const float* Vg = g_v + (size_t)b * Ntok * Cdim;

    for (int i = tid; i < 4096; i += 256) {
        int m = i >> 6, c4 = i & 63;
        float4 v = *(const float4*)(Qg + (size_t)m * Cdim + c4 * 4);
        *(float4*)(QS + m * QS_S + c4 * 4) = v;
    }

    float oacc[16][4];
    #pragma unroll
    for (int i = 0; i < 16; i++)
        #pragma unroll
        for (int j = 0; j < 4; j++) oacc[i][j] = 0.f;
    float mrun1 = -1e30f, mrun2 = -1e30f, lrun1 = 0.f, lrun2 = 0.f;

    for (int kt = 0; kt < 64; kt++) {
        __syncthreads();   // prev iter done with KS/VS/PS; Q staged (iter 0)
        int m0 = kt * 64;
        for (int i = tid; i < 4096; i += 256) {
            int m = i >> 6, c4 = i & 63;
            *(float4*)(KS + m * KS_S + c4 * 4) =
                *(const float4*)(Kg + (size_t)(m0 + m) * Cdim + c4 * 4);
            *(float4*)(VS + m * VS_S + c4 * 4) =
                *(const float4*)(Vg + (size_t)(m0 + m) * Cdim + c4 * 4);
        }
        __syncthreads();

        // ---- S = Q K^T : warp tile 16 x 32 ----
        float sacc[4][4];
        #pragma unroll
        for (int i = 0; i < 4; i++)
            #pragma unroll
            for (int j = 0; j < 4; j++) sacc[i][j] = 0.f;

        for (int k0 = 0; k0 < 256; k0 += 8) {
            const float* ap = QS + r1 * QS_S + k0 + tig;
            uint32_t a0 = __float_as_uint(ap[0]);
            uint32_t a1 = __float_as_uint(ap[8 * QS_S]);
            uint32_t a2 = __float_as_uint(ap[4]);
            uint32_t a3 = __float_as_uint(ap[8 * QS_S + 4]);
            #pragma unroll
            for (int nt = 0; nt < 4; nt++) {
                int m = half * 32 + nt * 8 + g;
                const float* bp = KS + m * KS_S + k0 + tig;
                mma_tf32(sacc[nt], a0, a1, a2, a3,
                         __float_as_uint(bp[0]), __float_as_uint(bp[4]));
            }
        }

        // ---- row max (intra-warp quad + cross-half via SMEM) ----
        float tmax1 = -1e30f, tmax2 = -1e30f;
        #pragma unroll
        for (int nt = 0; nt < 4; nt++) {
            tmax1 = fmaxf(tmax1, fmaxf(sacc[nt][0], sacc[nt][1]));
            tmax2 = fmaxf(tmax2, fmaxf(sacc[nt][2], sacc[nt][3]));
        }
        #pragma unroll
        for (int off = 1; off <= 2; off <<= 1) {
            tmax1 = fmaxf(tmax1, __shfl_xor_sync(0xffffffffu, tmax1, off));
            tmax2 = fmaxf(tmax2, __shfl_xor_sync(0xffffffffu, tmax2, off));
        }
        if (tig == 0) {
            RMAX[half * 64 + r1]     = tmax1;
            RMAX[half * 64 + r1 + 8] = tmax2;
        }
        __syncthreads();

        float mnew1 = fmaxf(mrun1, fmaxf(RMAX[r1],     RMAX[64 + r1]));
        float mnew2 = fmaxf(mrun2, fmaxf(RMAX[r1 + 8], RMAX[64 + r1 + 8]));

        // ---- exp, write P, partial row sums ----
        float sum1 = 0.f, sum2 = 0.f;
        #pragma unroll
        for (int nt = 0; nt < 4; nt++) {
            float p0 = __expf(sacc[nt][0] - mnew1);
            float p1 = __expf(sacc[nt][1] - mnew1);
            float p2 = __expf(sacc[nt][2] - mnew2);
            float p3 = __expf(sacc[nt][3] - mnew2);
            sum1 += p0 + p1;
            sum2 += p2 + p3;
            int mcol = half * 32 + nt * 8 + tig * 2;
            *(float2*)(PS + r1 * PS_S + mcol)       = make_float2(p0, p1);
            *(float2*)(PS + (r1 + 8) * PS_S + mcol) = make_float2(p2, p3);
        }
        #pragma unroll
        for (int off = 1; off <= 2; off <<= 1) {
            sum1 += __shfl_xor_sync(0xffffffffu, sum1, off);
            sum2 += __shfl_xor_sync(0xffffffffu, sum2, off);
        }
        if (tig == 0) {
            RSUM[half * 64 + r1]     = sum1;
            RSUM[half * 64 + r1 + 8] = sum2;
        }
        __syncthreads();

        float ls1 = RSUM[r1]     + RSUM[64 + r1];
        float ls2 = RSUM[r1 + 8] + RSUM[64 + r1 + 8];
        float al1 = __expf(mrun1 - mnew1);
        float al2 = __expf(mrun2 - mnew2);
        lrun1 = lrun1 * al1 + ls1;  mrun1 = mnew1;
        lrun2 = lrun2 * al2 + ls2;  mrun2 = mnew2;

        #pragma unroll
        for (int nt = 0; nt < 16; nt++) {
            oacc[nt][0] *= al1;  oacc[nt][1] *= al1;
            oacc[nt][2] *= al2;  oacc[nt][3] *= al2;
        }

        // ---- O += P V : warp tile 16 rows x 128 channels ----
        for (int k0 = 0; k0 < 64; k0 += 8) {
            const float* ap = PS + r1 * PS_S + k0 + tig;
            uint32_t a0 = __float_as_uint(ap[0]);
            uint32_t a1 = __float_as_uint(ap[8 * PS_S]);
            uint32_t a2 = __float_as_uint(ap[4]);
            uint32_t a3 = __float_as_uint(ap[8 * PS_S + 4]);
            #pragma unroll
            for (int nt = 0; nt < 16; nt++) {
                int c = half * 128 + nt * 8 + g;
                const float* bp = VS + (k0 + tig) * VS_S + c;
                mma_tf32(oacc[nt], a0, a1, a2, a3,
                         __float_as_uint(bp[0]),
                         __float_as_uint(bp[4 * VS_S]));
            }
        }
    }

    // ---- epilogue: out[b,c,n] = gamma * O/l + x ----
    float gmm = gamma_p[0];
    const float* xb = x   + (size_t)b * Cdim * Ntok;
    float*       ob = out + (size_t)b * Cdim * Ntok;
    float inv1 = 1.f / lrun1, inv2 = 1.f / lrun2;
    int n1 = q0 + r1, n2 = n1 + 8;
    #pragma unroll
    for (int nt = 0; nt < 16; nt++) {
        int c = half * 128 + nt * 8 + tig * 2;
        ob[(size_t)c * Ntok + n1]       = gmm * oacc[nt][0] * inv1 + xb[(size_t)c * Ntok + n1];
        ob[(size_t)(c + 1) * Ntok + n1] = gmm * oacc[nt][1] * inv1 + xb[(size_t)(c + 1) * Ntok + n1];
        ob[(size_t)c * Ntok + n2]       = gmm * oacc[nt][2] * inv2 + xb[(size_t)c * Ntok + n2];
        ob[(size_t)(c + 1) * Ntok + n2] = gmm * oacc[nt][3] * inv2 + xb[(size_t)(c + 1) * Ntok + n2];
    }
}

// ---------------------------------------------------------------------------
extern "C" void kernel_launch(void* const* d_in, const int* in_sizes, int n_in,
                              void* d_out, int out_size)
{
    const float* x     = (const float*)d_in[0];
    const float* wq    = (const float*)d_in[1];
    const float* bq    = (const float*)d_in[2];
    const float* wk    = (const float*)d_in[3];
    const float* bk    = (const float*)d_in[4];
    const float* wv    = (const float*)d_in[5];
    const float* bv    = (const float*)d_in[6];
    const float* gamma = (const float*)d_in[7];

    cudaFuncSetAttribute(proj_mma_kernel,
                         cudaFuncAttributeMaxDynamicSharedMemorySize, PROJ_SMEM);
    dim3 pgrid(Ntok / 64, Cdim / 64, 3 * Bsz);
    proj_mma_kernel<<<pgrid, 256, PROJ_SMEM>>>(x, wq, bq, wk, bk, wv, bv);

    cudaFuncSetAttribute(attn_mma_kernel,
                         cudaFuncAttributeMaxDynamicSharedMemorySize, ATTN_SMEM);
    dim3 agrid(Ntok / 64, Bsz);
    attn_mma_kernel<<<agrid, 256, ATTN_SMEM>>>(x, gamma, (float*)d_out);
}

// round 7
// speedup vs baseline: 4.7301x; 1.6519x over previous
#include <cuda_runtime.h>
#include <cuda_bf16.h>
#include <cstdint>

#define Bsz  8
#define Cdim 256
#define Ntok 4096

// Scratch (allocation-free rule): token-major [B][N][C], bf16
__device__ __nv_bfloat16 g_q[Bsz * Ntok * Cdim];
__device__ __nv_bfloat16 g_k[Bsz * Ntok * Cdim];
__device__ __nv_bfloat16 g_v[Bsz * Ntok * Cdim];

// ---------------------------------------------------------------------------
__device__ __forceinline__ uint32_t smaddr(const void* p) {
    return (uint32_t)__cvta_generic_to_shared(p);
}

__device__ __forceinline__ void mma_tf32(float* c,
    uint32_t a0, uint32_t a1, uint32_t a2, uint32_t a3,
    uint32_t b0, uint32_t b1)
{
    asm volatile(
        "mma.sync.aligned.m16n8k8.row.col.f32.tf32.tf32.f32 "
        "{%0,%1,%2,%3}, {%4,%5,%6,%7}, {%8,%9}, {%0,%1,%2,%3};\n"
        : "+f"(c[0]), "+f"(c[1]), "+f"(c[2]), "+f"(c[3])
        : "r"(a0), "r"(a1), "r"(a2), "r"(a3), "r"(b0), "r"(b1));
}

__device__ __forceinline__ void mma_bf16(float* c,
    uint32_t a0, uint32_t a1, uint32_t a2, uint32_t a3,
    uint32_t b0, uint32_t b1)
{
    asm volatile(
        "mma.sync.aligned.m16n8k16.row.col.f32.bf16.bf16.f32 "
        "{%0,%1,%2,%3}, {%4,%5,%6,%7}, {%8,%9}, {%0,%1,%2,%3};\n"
        : "+f"(c[0]), "+f"(c[1]), "+f"(c[2]), "+f"(c[3])
        : "r"(a0), "r"(a1), "r"(a2), "r"(a3), "r"(b0), "r"(b1));
}

__device__ __forceinline__ void ldm_x4(uint32_t& r0, uint32_t& r1,
                                       uint32_t& r2, uint32_t& r3, uint32_t addr)
{
    asm volatile("ldmatrix.sync.aligned.m8n8.x4.shared.b16 {%0,%1,%2,%3}, [%4];"
        : "=r"(r0), "=r"(r1), "=r"(r2), "=r"(r3) : "r"(addr));
}

__device__ __forceinline__ void ldm_x4_t(uint32_t& r0, uint32_t& r1,
                                         uint32_t& r2, uint32_t& r3, uint32_t addr)
{
    asm volatile("ldmatrix.sync.aligned.m8n8.x4.trans.shared.b16 {%0,%1,%2,%3}, [%4];"
        : "=r"(r0), "=r"(r1), "=r"(r2), "=r"(r3) : "r"(addr));
}

// ---------------------------------------------------------------------------
// Projection via tf32 mma (fp32 in), bf16 out: out[b,n,o] = W x + bias
// ---------------------------------------------------------------------------
#define PX_S 72
#define PW_S 260
#define PROJ_SMEM ((256 * PX_S + 64 * PW_S) * 4)

__global__ __launch_bounds__(256, 1) void proj_mma_kernel(
    const float* __restrict__ x,
    const float* __restrict__ wq, const float* __restrict__ bq,
    const float* __restrict__ wk, const float* __restrict__ bk,
    const float* __restrict__ wv, const float* __restrict__ bv)
{
    int z    = blockIdx.z;
    int proj = z >> 3;
    int b    = z & 7;

    const float* W; const float* bias; __nv_bfloat16* out;
    if (proj == 0)      { W = wq; bias = bq; out = g_q; }
    else if (proj == 1) { W = wk; bias = bk; out = g_k; }
    else                { W = wv; bias = bv; out = g_v; }

    int n0 = blockIdx.x * 64;
    int o0 = blockIdx.y * 64;

    extern __shared__ float sm[];
    float* Xs = sm;                 // [256 c][PX_S]  x[c][n]
    float* Ws = sm + 256 * PX_S;    // [64 o][PW_S]   W[o][c]

    int tid  = threadIdx.x;
    int lane = tid & 31;
    int warp = tid >> 5;
    int strip = warp & 3, half = warp >> 2;
    int g = lane >> 2, tig = lane & 3;

    const float* xb = x + (size_t)b * Cdim * Ntok;
    for (int i = tid; i < 4096; i += 256) {
        int cc = i >> 4, n4 = i & 15;
        float4 v = *(const float4*)(xb + (size_t)cc * Ntok + n0 + n4 * 4);
        *(float4*)(Xs + cc * PX_S + n4 * 4) = v;
    }
    for (int i = tid; i < 4096; i += 256) {
        int oo = i >> 6, c4 = i & 63;
        float4 v = *(const float4*)(W + (size_t)(o0 + oo) * Cdim + c4 * 4);
        *(float4*)(Ws + oo * PW_S + c4 * 4) = v;
    }
    __syncthreads();

    float acc[4][4];
    #pragma unroll
    for (int i = 0; i < 4; i++)
        #pragma unroll
        for (int j = 0; j < 4; j++) acc[i][j] = 0.f;

    for (int k0 = 0; k0 < 256; k0 += 8) {
        const float* ap = Xs + (k0 + tig) * PX_S + strip * 16 + g;
        uint32_t a0 = __float_as_uint(ap[0]);
        uint32_t a1 = __float_as_uint(ap[8]);
        uint32_t a2 = __float_as_uint(ap[4 * PX_S]);
        uint32_t a3 = __float_as_uint(ap[4 * PX_S + 8]);
        #pragma unroll
        for (int nt = 0; nt < 4; nt++) {
            int o = half * 32 + nt * 8 + g;
            const float* bp = Ws + o * PW_S + k0 + tig;
            mma_tf32(acc[nt], a0, a1, a2, a3,
                     __float_as_uint(bp[0]), __float_as_uint(bp[4]));
        }
    }

    __nv_bfloat16* ob = out + ((size_t)b * Ntok + n0) * Cdim;
    int n1 = strip * 16 + g;
    #pragma unroll
    for (int nt = 0; nt < 4; nt++) {
        int o = o0 + half * 32 + nt * 8 + tig * 2;
        float b0v = bias[o], b1v = bias[o + 1];
        *(__nv_bfloat162*)(ob + (size_t)n1 * Cdim + o) =
            __floats2bfloat162_rn(acc[nt][0] + b0v, acc[nt][1] + b1v);
        *(__nv_bfloat162*)(ob + (size_t)(n1 + 8) * Cdim + o) =
            __floats2bfloat162_rn(acc[nt][2] + b0v, acc[nt][3] + b1v);
    }
}

// ---------------------------------------------------------------------------
// Flash attention, bf16 mma m16n8k16 + ldmatrix. 64-query block, 8 warps.
// ---------------------------------------------------------------------------
#define QS_S 264   // bf16 units per row (512B data + 16B pad); 33x16B -> odd stride
#define KS_S 264
#define VS_S 264
#define PS_S2 72   // 9x16B
#define ATTN_BF16S (3 * 64 * 264 + 64 * 72)
#define ATTN_SMEM (ATTN_BF16S * 2 + 256 * 4)

__global__ __launch_bounds__(256, 1) void attn_mma_kernel(
    const float* __restrict__ x,
    const float* __restrict__ gamma_p,
    float* __restrict__ out)
{
    extern __shared__ __nv_bfloat16 smb[];
    __nv_bfloat16* QS = smb;                    // [64][QS_S]
    __nv_bfloat16* KS = QS + 64 * QS_S;         // [64][KS_S]
    __nv_bfloat16* VS = KS + 64 * KS_S;         // [64][VS_S]
    __nv_bfloat16* PS = VS + 64 * VS_S;         // [64][PS_S2]
    float* RMAX = (float*)(PS + 64 * PS_S2);    // [2][64]
    float* RSUM = RMAX + 128;                   // [2][64]

    int b  = blockIdx.y;
    int q0 = blockIdx.x * 64;
    int tid  = threadIdx.x;
    int warp = tid >> 5, lane = tid & 31;
    int strip = warp & 3, half = warp >> 2;
    int g = lane >> 2, tig = lane & 3;
    int r1 = strip * 16 + g;                    // frag rows r1, r1+8

    const __nv_bfloat16* Qg = g_q + ((size_t)b * Ntok + q0) * Cdim;
    const __nv_bfloat16* Kg = g_k + (size_t)b * Ntok * Cdim;
    const __nv_bfloat16* Vg = g_v + (size_t)b * Ntok * Cdim;

    // Stage Q (64 rows x 256 bf16; float4 = 8 bf16)
    for (int i = tid; i < 2048; i += 256) {
        int m = i >> 5, s = i & 31;
        float4 v = ((const float4*)Qg)[m * 32 + s];
        *(float4*)(QS + m * QS_S + s * 8) = v;
    }

    // ldmatrix lane addresses (sel = lane>>3 picks matrix)
    uint32_t aQ = smaddr(QS + (strip * 16 + ((lane >> 3) & 1) * 8 + (lane & 7)) * QS_S
                            + ((lane >> 4) & 1) * 8);
    uint32_t bK = smaddr(KS + (half * 32 + ((lane >> 4) & 1) * 8 + (lane & 7)) * KS_S
                            + ((lane >> 3) & 1) * 8);
    uint32_t aP = smaddr(PS + (strip * 16 + ((lane >> 3) & 1) * 8 + (lane & 7)) * PS_S2
                            + ((lane >> 4) & 1) * 8);
    uint32_t bV = smaddr(VS + (((lane >> 3) & 1) * 8 + (lane & 7)) * VS_S
                            + half * 128 + ((lane >> 4) & 1) * 8);

    float oacc[16][4];
    #pragma unroll
    for (int i = 0; i < 16; i++)
        #pragma unroll
        for (int j = 0; j < 4; j++) oacc[i][j] = 0.f;
    float mrun1 = -1e30f, mrun2 = -1e30f, lrun1 = 0.f, lrun2 = 0.f;

    for (int kt = 0; kt < 64; kt++) {
        __syncthreads();   // prev iter done with KS/VS/PS (and Q staged, iter 0)
        int m0 = kt * 64;
        const float4* Kg4 = (const float4*)(Kg + (size_t)m0 * Cdim);
        const float4* Vg4 = (const float4*)(Vg + (size_t)m0 * Cdim);
        for (int i = tid; i < 2048; i += 256) {
            int m = i >> 5, s = i & 31;
            *(float4*)(KS + m * KS_S + s * 8) = Kg4[m * 32 + s];
            *(float4*)(VS + m * VS_S + s * 8) = Vg4[m * 32 + s];
        }
        __syncthreads();

        // ---- S = Q K^T : 16 k-steps of k16; warp tile 16x32 ----
        float sacc[4][4];
        #pragma unroll
        for (int i = 0; i < 4; i++)
            #pragma unroll
            for (int j = 0; j < 4; j++) sacc[i][j] = 0.f;

        #pragma unroll 4
        for (int k = 0; k < 16; k++) {
            uint32_t a0, a1, a2, a3, b0, b1, b2, b3;
            ldm_x4(a0, a1, a2, a3, aQ + k * 32);
            ldm_x4(b0, b1, b2, b3, bK + k * 32);
            mma_bf16(sacc[0], a0, a1, a2, a3, b0, b1);
            mma_bf16(sacc[1], a0, a1, a2, a3, b2, b3);
            ldm_x4(b0, b1, b2, b3, bK + 16 * KS_S * 2 + k * 32);
            mma_bf16(sacc[2], a0, a1, a2, a3, b0, b1);
            mma_bf16(sacc[3], a0, a1, a2, a3, b2, b3);
        }

        // ---- row max (quad shuffle + cross-half via SMEM) ----
        float tmax1 = -1e30f, tmax2 = -1e30f;
        #pragma unroll
        for (int nt = 0; nt < 4; nt++) {
            tmax1 = fmaxf(tmax1, fmaxf(sacc[nt][0], sacc[nt][1]));
            tmax2 = fmaxf(tmax2, fmaxf(sacc[nt][2], sacc[nt][3]));
        }
        #pragma unroll
        for (int off = 1; off <= 2; off <<= 1) {
            tmax1 = fmaxf(tmax1, __shfl_xor_sync(0xffffffffu, tmax1, off));
            tmax2 = fmaxf(tmax2, __shfl_xor_sync(0xffffffffu, tmax2, off));
        }
        if (tig == 0) {
            RMAX[half * 64 + r1]     = tmax1;
            RMAX[half * 64 + r1 + 8] = tmax2;
        }
        __syncthreads();

        float mnew1 = fmaxf(mrun1, fmaxf(RMAX[r1],     RMAX[64 + r1]));
        float mnew2 = fmaxf(mrun2, fmaxf(RMAX[r1 + 8], RMAX[64 + r1 + 8]));

        // ---- exp, write P (bf16), partial sums ----
        float sum1 = 0.f, sum2 = 0.f;
        #pragma unroll
        for (int nt = 0; nt < 4; nt++) {
            float p0 = __expf(sacc[nt][0] - mnew1);
            float p1 = __expf(sacc[nt][1] - mnew1);
            float p2 = __expf(sacc[nt][2] - mnew2);
            float p3 = __expf(sacc[nt][3] - mnew2);
            sum1 += p0 + p1;
            sum2 += p2 + p3;
            int mcol = half * 32 + nt * 8 + tig * 2;
            *(__nv_bfloat162*)(PS + r1 * PS_S2 + mcol)       = __floats2bfloat162_rn(p0, p1);
            *(__nv_bfloat162*)(PS + (r1 + 8) * PS_S2 + mcol) = __floats2bfloat162_rn(p2, p3);
        }
        #pragma unroll
        for (int off = 1; off <= 2; off <<= 1) {
            sum1 += __shfl_xor_sync(0xffffffffu, sum1, off);
            sum2 += __shfl_xor_sync(0xffffffffu, sum2, off);
        }
        if (tig == 0) {
            RSUM[half * 64 + r1]     = sum1;
            RSUM[half * 64 + r1 + 8] = sum2;
        }
        __syncthreads();

        float ls1 = RSUM[r1]     + RSUM[64 + r1];
        float ls2 = RSUM[r1 + 8] + RSUM[64 + r1 + 8];
        float al1 = __expf(mrun1 - mnew1);
        float al2 = __expf(mrun2 - mnew2);
        lrun1 = lrun1 * al1 + ls1;  mrun1 = mnew1;
        lrun2 = lrun2 * al2 + ls2;  mrun2 = mnew2;

        #pragma unroll
        for (int nt = 0; nt < 16; nt++) {
            oacc[nt][0] *= al1;  oacc[nt][1] *= al1;
            oacc[nt][2] *= al2;  oacc[nt][3] *= al2;
        }

        // ---- O += P V : 4 k-steps (64 keys), warp tile 16x128 ----
        #pragma unroll
        for (int km = 0; km < 4; km++) {
            uint32_t a0, a1, a2, a3;
            ldm_x4(a0, a1, a2, a3, aP + km * 32);
            #pragma unroll
            for (int ntp = 0; ntp < 16; ntp += 2) {
                uint32_t b0, b1, b2, b3;
                ldm_x4_t(b0, b1, b2, b3, bV + (km * 16 * VS_S + ntp * 8) * 2);
                mma_bf16(oacc[ntp],     a0, a1, a2, a3, b0, b1);
                mma_bf16(oacc[ntp + 1], a0, a1, a2, a3, b2, b3);
            }
        }
    }

    // ---- epilogue: out[b,c,n] = gamma * O/l + x ----
    float gmm = gamma_p[0];
    const float* xb = x   + (size_t)b * Cdim * Ntok;
    float*       ob = out + (size_t)b * Cdim * Ntok;
    float inv1 = 1.f / lrun1, inv2 = 1.f / lrun2;
    int n1 = q0 + r1, n2 = n1 + 8;
    #pragma unroll
    for (int nt = 0; nt < 16; nt++) {
        int c = half * 128 + nt * 8 + tig * 2;
        ob[(size_t)c * Ntok + n1]       = gmm * oacc[nt][0] * inv1 + xb[(size_t)c * Ntok + n1];
        ob[(size_t)(c + 1) * Ntok + n1] = gmm * oacc[nt][1] * inv1 + xb[(size_t)(c + 1) * Ntok + n1];
        ob[(size_t)c * Ntok + n2]       = gmm * oacc[nt][2] * inv2 + xb[(size_t)c * Ntok + n2];
        ob[(size_t)(c + 1) * Ntok + n2] = gmm * oacc[nt][3] * inv2 + xb[(size_t)(c + 1) * Ntok + n2];
    }
}

// ---------------------------------------------------------------------------
extern "C" void kernel_launch(void* const* d_in, const int* in_sizes, int n_in,
                              void* d_out, int out_size)
{
    const float* x     = (const float*)d_in[0];
    const float* wq    = (const float*)d_in[1];
    const float* bq    = (const float*)d_in[2];
    const float* wk    = (const float*)d_in[3];
    const float* bk    = (const float*)d_in[4];
    const float* wv    = (const float*)d_in[5];
    const float* bv    = (const float*)d_in[6];
    const float* gamma = (const float*)d_in[7];

    cudaFuncSetAttribute(proj_mma_kernel,
                         cudaFuncAttributeMaxDynamicSharedMemorySize, PROJ_SMEM);
    dim3 pgrid(Ntok / 64, Cdim / 64, 3 * Bsz);
    proj_mma_kernel<<<pgrid, 256, PROJ_SMEM>>>(x, wq, bq, wk, bk, wv, bv);

    cudaFuncSetAttribute(attn_mma_kernel,
                         cudaFuncAttributeMaxDynamicSharedMemorySize, ATTN_SMEM);
    dim3 agrid(Ntok / 64, Bsz);
    attn_mma_kernel<<<agrid, 256, ATTN_SMEM>>>(x, gamma, (float*)d_out);
}